// round 1
// baseline (speedup 1.0000x reference)
#include <cuda_runtime.h>
#include <math.h>

// ---------------- problem constants ----------------
#define NTOT 310000
#define C 64

static const int H_N[5]    = {50000,100000,100000,40000,20000};
static const int H_XOFF[5] = {0,50000,150000,250000,290000};
static const int H_PI[15]  = {0,1,2,3,4,0,0,0,0,1,1,1,2,2,3};
static const int H_PJ[15]  = {0,1,2,3,4,1,2,3,4,2,3,4,3,4,4};
static const int H_EOFF[15]= {0,400000,1200000,2000000,2320000,2480000,3280000,
                              4080000,4400000,4560000,5360000,5680000,5840000,
                              6160000,6320000};
static const int H_ESZ[15] = {400000,800000,800000,320000,160000,800000,800000,
                              320000,160000,800000,320000,160000,320000,160000,160000};

__constant__ int c_N[5]  = {50000,100000,100000,40000,20000};
__constant__ int c_XO[5] = {0,50000,150000,250000,290000};

// ---------------- device scratch ----------------
__device__ float g_X[(size_t)NTOT*C];      // current node features (79MB)
__device__ float g_H[(size_t)NTOT*C];      // accumulator (79MB)
__device__ float g_S[(size_t)100000*C];    // per-pair sparse-agg scratch (25.6MB)
__device__ float g_sum[320];
__device__ float g_sq[320];
__device__ int   g_mx[320];
__device__ int   g_mn[320];
__device__ float g_pooled[1284];
__device__ float g_h1[512];

// ---------------- helpers ----------------
__device__ __forceinline__ int fenc(float f) {
    int i = __float_as_int(f);
    return i >= 0 ? i : (i ^ 0x7fffffff);
}
__device__ __forceinline__ float fdec(int i) {
    return __int_as_float(i >= 0 ? i : (i ^ 0x7fffffff));
}

// ---------------- kernels ----------------

// concat x_0..x_4 -> g_X (float4 path)
__global__ void k_init(const float4* __restrict__ x0, const float4* __restrict__ x1,
                       const float4* __restrict__ x2, const float4* __restrict__ x3,
                       const float4* __restrict__ x4) {
    const int B1 = 800000, B2 = 2400000, B3 = 4000000, B4 = 4640000, B5 = 4960000;
    float4* X = (float4*)g_X;
    for (int i = blockIdx.x * blockDim.x + threadIdx.x; i < B5;
         i += gridDim.x * blockDim.x) {
        float4 v;
        if      (i < B1) v = x0[i];
        else if (i < B2) v = x1[i - B1];
        else if (i < B3) v = x2[i - B2];
        else if (i < B4) v = x3[i - B3];
        else             v = x4[i - B4];
        X[i] = v;
    }
}

// sparse aggregation: S[r,:] = sum_{e: rows[e]==r} vals[e] * X_i[cols[e],:]
// rows sorted ascending within the pair segment -> warp owns 4 dst rows,
// binary-searches its edge span, accumulates in registers, no atomics.
__global__ void k_agg(const int* __restrict__ rows, const int* __restrict__ cols,
                      const float* __restrict__ vals, int E, int xoffi, int Nj) {
    int warp = (blockIdx.x * blockDim.x + threadIdx.x) >> 5;
    int lane = threadIdx.x & 31;
    int r0 = warp * 4;
    if (r0 >= Nj) return;
    int r1 = min(r0 + 4, Nj);

    // lower_bound(rows, r0)
    int lo = 0, hi = E;
    while (lo < hi) { int m = (lo + hi) >> 1; if (__ldg(rows + m) < r0) lo = m + 1; else hi = m; }
    int e = lo;
    // lower_bound(rows, r1)
    hi = E;
    while (lo < hi) { int m = (lo + hi) >> 1; if (__ldg(rows + m) < r1) lo = m + 1; else hi = m; }
    int eend = lo;

    const float* X = g_X + (size_t)xoffi * C;
    int c0 = lane * 2;

    int rr = (e < eend) ? __ldg(rows + e) : 0x7fffffff;
    for (int r = r0; r < r1; ++r) {
        float ax = 0.f, ay = 0.f;
        while (rr == r) {
            int   cc = __ldg(cols + e);
            float v  = __ldg(vals + e);
            float2 xv = *(const float2*)(X + (size_t)cc * C + c0);
            ax = fmaf(v, xv.x, ax);
            ay = fmaf(v, xv.y, ay);
            ++e;
            rr = (e < eend) ? __ldg(rows + e) : 0x7fffffff;
        }
        *(float2*)(g_S + (size_t)r * C + c0) = make_float2(ax, ay);
    }
}

// H_j[r,:] (+)= S[r,:] @ W   (64x64), 64 rows per block, 4x4 per thread
__global__ void k_gemm(const float* __restrict__ W, int Nj, int hoff, int accum) {
    __shared__ float sW[64 * 64];
    __shared__ float sS[64 * 65];
    int tid = threadIdx.x;            // 256
    int rowBase = blockIdx.x * 64;
    float* Hb = g_H + (size_t)hoff * C;

    #pragma unroll
    for (int t = tid; t < 4096; t += 256) sW[t] = W[t];
    for (int t = tid; t < 4096; t += 256) {
        int r = t >> 6, c = t & 63;
        int gr = rowBase + r;
        sS[r * 65 + c] = (gr < Nj) ? g_S[(size_t)gr * C + c] : 0.f;
    }
    __syncthreads();

    int cq = tid & 15, rq = tid >> 4;
    int c0 = cq * 4, r0 = rq * 4;

    float acc[4][4];
    #pragma unroll
    for (int r = 0; r < 4; ++r) {
        int gr = rowBase + r0 + r;
        if (accum && gr < Nj) {
            float4 h = *(const float4*)(Hb + (size_t)gr * C + c0);
            acc[r][0] = h.x; acc[r][1] = h.y; acc[r][2] = h.z; acc[r][3] = h.w;
        } else {
            acc[r][0] = acc[r][1] = acc[r][2] = acc[r][3] = 0.f;
        }
    }

    #pragma unroll 8
    for (int a = 0; a < 64; ++a) {
        float4 w = *(const float4*)(sW + a * 64 + c0);
        float s0 = sS[(r0 + 0) * 65 + a];
        float s1 = sS[(r0 + 1) * 65 + a];
        float s2 = sS[(r0 + 2) * 65 + a];
        float s3 = sS[(r0 + 3) * 65 + a];
        acc[0][0] = fmaf(s0, w.x, acc[0][0]); acc[0][1] = fmaf(s0, w.y, acc[0][1]);
        acc[0][2] = fmaf(s0, w.z, acc[0][2]); acc[0][3] = fmaf(s0, w.w, acc[0][3]);
        acc[1][0] = fmaf(s1, w.x, acc[1][0]); acc[1][1] = fmaf(s1, w.y, acc[1][1]);
        acc[1][2] = fmaf(s1, w.z, acc[1][2]); acc[1][3] = fmaf(s1, w.w, acc[1][3]);
        acc[2][0] = fmaf(s2, w.x, acc[2][0]); acc[2][1] = fmaf(s2, w.y, acc[2][1]);
        acc[2][2] = fmaf(s2, w.z, acc[2][2]); acc[2][3] = fmaf(s2, w.w, acc[2][3]);
        acc[3][0] = fmaf(s3, w.x, acc[3][0]); acc[3][1] = fmaf(s3, w.y, acc[3][1]);
        acc[3][2] = fmaf(s3, w.z, acc[3][2]); acc[3][3] = fmaf(s3, w.w, acc[3][3]);
    }

    #pragma unroll
    for (int r = 0; r < 4; ++r) {
        int gr = rowBase + r0 + r;
        if (gr < Nj) {
            *(float4*)(Hb + (size_t)gr * C + c0) =
                make_float4(acc[r][0], acc[r][1], acc[r][2], acc[r][3]);
        }
    }
}

// X = relu(H (+ X if resid))
__global__ void k_relu(int resid) {
    float4* X = (float4*)g_X;
    const float4* Hp = (const float4*)g_H;
    const int n = NTOT * 16;
    for (int i = blockIdx.x * blockDim.x + threadIdx.x; i < n;
         i += gridDim.x * blockDim.x) {
        float4 h = Hp[i];
        if (resid) {
            float4 x = X[i];
            h.x += x.x; h.y += x.y; h.z += x.z; h.w += x.w;
        }
        h.x = fmaxf(h.x, 0.f); h.y = fmaxf(h.y, 0.f);
        h.z = fmaxf(h.z, 0.f); h.w = fmaxf(h.w, 0.f);
        X[i] = h;
    }
}

__global__ void k_pool_init() {
    int t = threadIdx.x;
    if (t < 320) {
        g_sum[t] = 0.f; g_sq[t] = 0.f;
        g_mx[t] = 0x80000000; g_mn[t] = 0x7fffffff;
    }
}

// per-rank per-column partial stats
__global__ void k_pool() {
    int rank = blockIdx.y;
    int c = threadIdx.x & 63;
    int rg = threadIdx.x >> 6;          // 0..3
    int Nr = c_N[rank];
    const float* base = g_X + (size_t)c_XO[rank] * C;
    float s = 0.f, sq = 0.f, mx = -3.402823466e38f, mn = 3.402823466e38f;
    for (int r = blockIdx.x * 4 + rg; r < Nr; r += gridDim.x * 4) {
        float v = base[(size_t)r * C + c];
        s += v; sq = fmaf(v, v, sq);
        mx = fmaxf(mx, v); mn = fminf(mn, v);
    }
    int o = rank * 64 + c;
    atomicAdd(&g_sum[o], s);
    atomicAdd(&g_sq[o], sq);
    atomicMax(&g_mx[o], fenc(mx));
    atomicMin(&g_mn[o], fenc(mn));
}

__global__ void k_pool_fin(const float* __restrict__ gf) {
    int idx = blockIdx.x * blockDim.x + threadIdx.x;
    if (idx >= 1284) return;
    if (idx >= 1280) { g_pooled[idx] = gf[idx - 1280]; return; }
    int rank = idx >> 8;
    int part = (idx >> 6) & 3;
    int c = idx & 63;
    int o = rank * 64 + c;
    float Nr = (float)c_N[rank];
    float val;
    if (part == 0) val = g_sum[o] / Nr;
    else if (part == 1) {
        float m = g_sum[o] / Nr;
        float var = g_sq[o] / Nr - m * m;
        var = fmaxf(var, 0.f);
        if (var == 0.f) var = 1e-6f;
        val = sqrtf(var);
    } else if (part == 2) val = fdec(g_mx[o]);
    else val = fdec(g_mn[o]);
    g_pooled[idx] = val;
}

// fc1: [1,1284] @ [1284,512] -> relu -> g_h1. 16 blocks x 32 outputs.
__global__ void k_fc1(const float* __restrict__ w, const float* __restrict__ b) {
    __shared__ float p[1284];
    __shared__ float red[256];
    for (int i = threadIdx.x; i < 1284; i += 256) p[i] = g_pooled[i];
    __syncthreads();
    int lane = threadIdx.x & 31;
    int rp = threadIdx.x >> 5;          // 0..7
    int o = blockIdx.x * 32 + lane;
    float s = 0.f;
    for (int i = rp; i < 1284; i += 8) s = fmaf(p[i], w[(size_t)i * 512 + o], s);
    red[threadIdx.x] = s;
    __syncthreads();
    if (rp == 0) {
        float t = s;
        #pragma unroll
        for (int q = 1; q < 8; ++q) t += red[q * 32 + lane];
        t += b[o];
        g_h1[o] = fmaxf(t, 0.f);
    }
}

// fc2 -> fc3 -> fc4 -> final (out1 squared)
__global__ void k_tail(const float* __restrict__ w2, const float* __restrict__ b2,
                       const float* __restrict__ w3, const float* __restrict__ b3,
                       const float* __restrict__ w4, const float* __restrict__ b4,
                       float* __restrict__ out) {
    __shared__ float h2[128];
    __shared__ float h3[64];
    int tid = threadIdx.x;   // 128
    {
        float s = b2[tid];
        for (int i = 0; i < 512; ++i) s = fmaf(g_h1[i], w2[(size_t)i * 128 + tid], s);
        h2[tid] = fmaxf(s, 0.f);
    }
    __syncthreads();
    if (tid < 64) {
        float s = b3[tid];
        for (int i = 0; i < 128; ++i) s = fmaf(h2[i], w3[(size_t)i * 64 + tid], s);
        h3[tid] = fmaxf(s, 0.f);
    }
    __syncthreads();
    if (tid < 2) {
        float s = b4[tid];
        for (int i = 0; i < 64; ++i) s = fmaf(h3[i], w4[(size_t)i * 2 + tid], s);
        out[tid] = (tid == 0) ? s : s * s;
    }
}

// ---------------- host launcher ----------------
extern "C" void kernel_launch(void* const* d_in, const int* in_sizes, int n_in,
                              void* d_out, int out_size) {
    const float* x0 = (const float*)d_in[0];
    const float* x1 = (const float*)d_in[1];
    const float* x2 = (const float*)d_in[2];
    const float* x3 = (const float*)d_in[3];
    const float* x4 = (const float*)d_in[4];
    const int*   rows = (const int*)d_in[5];
    const int*   cols = (const int*)d_in[6];
    const float* vals = (const float*)d_in[7];
    const float* gf   = (const float*)d_in[8];
    const float* Whmc = (const float*)d_in[9];
    const float* fc1w = (const float*)d_in[10];
    const float* fc1b = (const float*)d_in[11];
    const float* fc2w = (const float*)d_in[12];
    const float* fc2b = (const float*)d_in[13];
    const float* fc3w = (const float*)d_in[14];
    const float* fc3b = (const float*)d_in[15];
    const float* fc4w = (const float*)d_in[16];
    const float* fc4b = (const float*)d_in[17];
    float* out = (float*)d_out;

    k_init<<<4096, 256>>>((const float4*)x0, (const float4*)x1, (const float4*)x2,
                          (const float4*)x3, (const float4*)x4);

    for (int l = 0; l < 3; ++l) {
        for (int k = 0; k < 15; ++k) {
            int i = H_PI[k], j = H_PJ[k];
            int Nj = H_N[j];
            int E  = H_ESZ[k];
            int eo = H_EOFF[k];
            int aggBlocks  = (Nj + 31) / 32;   // 8 warps/block, 4 rows/warp
            int gemmBlocks = (Nj + 63) / 64;
            k_agg<<<aggBlocks, 256>>>(rows + eo, cols + eo, vals + eo, E,
                                      H_XOFF[i], Nj);
            k_gemm<<<gemmBlocks, 256>>>(Whmc + (size_t)(l * 15 + k) * 4096,
                                        Nj, H_XOFF[j], (i != j) ? 1 : 0);
        }
        k_relu<<<2048, 256>>>(l == 2 ? 1 : 0);
    }

    k_pool_init<<<1, 320>>>();
    k_pool<<<dim3(32, 5), 256>>>();
    k_pool_fin<<<6, 256>>>(gf);
    k_fc1<<<16, 256>>>(fc1w, fc1b);
    k_tail<<<1, 128>>>(fc2w, fc2b, fc3w, fc3b, fc4w, fc4b, out);
}

// round 2
// speedup vs baseline: 1.7331x; 1.7331x over previous
#include <cuda_runtime.h>
#include <math.h>

typedef unsigned long long ull;

// ---------------- problem constants ----------------
#define C 64
#define NTOT 310000
#define NPAIRS 15
#define TOTAL_E 6480000
#define TOTAL_S 810000
#define TOTAL_G 202500

static const int H_XOFF[5] = {0,50000,150000,250000,290000};
static const int H_PI[15]  = {0,1,2,3,4,0,0,0,0,1,1,1,2,2,3};

__constant__ int c_EOFF[16] = {0,400000,1200000,2000000,2320000,2480000,3280000,
                               4080000,4400000,4560000,5360000,5680000,5840000,
                               6160000,6320000,6480000};
__constant__ int c_SOFF[16] = {0,50000,150000,250000,290000,310000,410000,510000,
                               550000,570000,670000,710000,730000,770000,790000,810000};
__constant__ int c_SPOFF[16] = {0,12500,37500,62500,72500,77500,102500,127500,
                                137500,142500,167500,177500,182500,192500,197500,202500};
__constant__ int c_NJP[15] = {50000,100000,100000,40000,20000,100000,100000,40000,
                              20000,100000,40000,20000,40000,20000,20000};
// agg block ranges: 8 warps/block, 4 rows/warp -> 32 rows/block
__constant__ int c_ABLK[16] = {0,1563,4688,7813,9063,9688,12813,15938,17188,17813,
                               20938,22188,22813,24063,24688,25313};
// gemm block ranges per destination rank j (64 rows/block)
__constant__ int c_GBLK[6] = {0,782,2345,3908,4533,4846};
__constant__ int c_JN[5]  = {50000,100000,100000,40000,20000};
__constant__ int c_JXO[5] = {0,50000,150000,250000,290000};
__constant__ int c_NPJ[5] = {1,2,3,4,5};
__constant__ int c_PAIRK[5][5] = {{0,0,0,0,0},{1,5,0,0,0},{2,6,9,0,0},
                                  {3,7,10,12,0},{4,8,11,13,14}};
__constant__ int c_N5[5]  = {50000,100000,100000,40000,20000};

// ---------------- device scratch ----------------
__device__ float g_X[(size_t)NTOT*C];          // node features (79MB)
__device__ float g_S[(size_t)TOTAL_S*C];       // per-pair agg scratch (207MB)
__device__ int   g_wspan[TOTAL_G];
__device__ float g_sum[320];
__device__ float g_sq[320];
__device__ int   g_mx[320];
__device__ int   g_mn[320];
__device__ float g_pooled[1284];
__device__ float g_h1[512];

struct AggParams { const float* src[15]; };

// ---------------- helpers ----------------
__device__ __forceinline__ int fenc(float f) {
    int i = __float_as_int(f);
    return i >= 0 ? i : (i ^ 0x7fffffff);
}
__device__ __forceinline__ float fdec(int i) {
    return __int_as_float(i >= 0 ? i : (i ^ 0x7fffffff));
}
__device__ __forceinline__ ull dup2(float v) {
    ull r; asm("mov.b64 %0,{%1,%1};" : "=l"(r) : "f"(v)); return r;
}
__device__ __forceinline__ void fma2(ull& acc, ull a, ull b) {
    asm("fma.rn.f32x2 %0,%1,%2,%0;" : "+l"(acc) : "l"(a), "l"(b));
}
__device__ __forceinline__ float2 unpack2(ull v) {
    float2 f; asm("mov.b64 {%0,%1},%2;" : "=f"(f.x), "=f"(f.y) : "l"(v)); return f;
}

// ---------------- span precompute ----------------
// g_wspan[SPOFF[k]+g] = min{ e : rows_k[e] >= 4*g }, default E_k
__global__ void k_span_fill() {
    for (int i = blockIdx.x * blockDim.x + threadIdx.x; i < TOTAL_G;
         i += gridDim.x * blockDim.x) {
        int k = 0;
        while (i >= c_SPOFF[k + 1]) ++k;
        g_wspan[i] = c_EOFF[k + 1] - c_EOFF[k];
    }
}
__global__ void k_span_mark(const int* __restrict__ rows) {
    for (int e = blockIdx.x * blockDim.x + threadIdx.x; e < TOTAL_E;
         e += gridDim.x * blockDim.x) {
        int k = 0;
        while (e >= c_EOFF[k + 1]) ++k;
        int le = e - c_EOFF[k];
        int r  = rows[e];
        int rp = (le > 0) ? rows[e - 1] : -1;
        if (r > rp) {
            int g0 = (rp >> 2) + 1;      // rp=-1 -> g0=0 (arith shift)
            int g1 = r >> 2;
            int* w = g_wspan + c_SPOFF[k];
            for (int g = g0; g <= g1; ++g) w[g] = le;
        }
    }
}

// ---------------- sparse aggregation (all 15 pairs, one launch) ----------------
__global__ void k_agg(AggParams P, const int* __restrict__ rows,
                      const int* __restrict__ cols, const float* __restrict__ vals,
                      const int* __restrict__ wspan) {
    int b = blockIdx.x;
    int k = 0;
    while (b >= c_ABLK[k + 1]) ++k;
    int warp = (b - c_ABLK[k]) * 8 + (threadIdx.x >> 5);
    int groups = c_NJP[k] >> 2;
    if (warp >= groups) return;
    int lane = threadIdx.x & 31;
    int c0 = lane * 2;
    int r0 = warp * 4;

    int E = c_EOFF[k + 1] - c_EOFF[k];
    const int*   prow = rows + c_EOFF[k];
    const int*   pcol = cols + c_EOFF[k];
    const float* pval = vals + c_EOFF[k];
    const int*   sp   = wspan + c_SPOFF[k];
    const float* src  = P.src[k];

    int es = __ldg(sp + warp);
    int ee = (warp + 1 < groups) ? __ldg(sp + warp + 1) : E;

    float2 a0 = make_float2(0.f, 0.f), a1 = a0, a2 = a0, a3 = a0;

    if (es < ee) {
        int eb   = es & ~3;
        int eend = (ee + 3) & ~3;   // E is a multiple of 4 -> stays in range
        #pragma unroll 2
        for (int e = eb; e < eend; e += 4) {
            int4   rr = *(const int4*)(prow + e);
            int4   cc = *(const int4*)(pcol + e);
            float4 vv = *(const float4*)(pval + e);
            float2 x0 = *(const float2*)(src + (size_t)cc.x * C + c0);
            float2 x1 = *(const float2*)(src + (size_t)cc.y * C + c0);
            float2 x2 = *(const float2*)(src + (size_t)cc.z * C + c0);
            float2 x3 = *(const float2*)(src + (size_t)cc.w * C + c0);
            int rrt[4] = {rr.x, rr.y, rr.z, rr.w};
            float vvt[4] = {vv.x, vv.y, vv.z, vv.w};
            float2 xt[4] = {x0, x1, x2, x3};
            #pragma unroll
            for (int t = 0; t < 4; ++t) {
                int d = rrt[t] - r0;
                float vm;
                vm = (d == 0) ? vvt[t] : 0.f;
                a0.x = fmaf(vm, xt[t].x, a0.x); a0.y = fmaf(vm, xt[t].y, a0.y);
                vm = (d == 1) ? vvt[t] : 0.f;
                a1.x = fmaf(vm, xt[t].x, a1.x); a1.y = fmaf(vm, xt[t].y, a1.y);
                vm = (d == 2) ? vvt[t] : 0.f;
                a2.x = fmaf(vm, xt[t].x, a2.x); a2.y = fmaf(vm, xt[t].y, a2.y);
                vm = (d == 3) ? vvt[t] : 0.f;
                a3.x = fmaf(vm, xt[t].x, a3.x); a3.y = fmaf(vm, xt[t].y, a3.y);
            }
        }
    }
    float* S = g_S + (size_t)(c_SOFF[k] + r0) * C + c0;
    *(float2*)(S)         = a0;
    *(float2*)(S + C)     = a1;
    *(float2*)(S + 2 * C) = a2;
    *(float2*)(S + 3 * C) = a3;
}

// ---------------- fused GEMM + residual + relu (all pairs of one layer) --------
// block owns 64 rows of destination j; loops over all pairs k feeding j.
__global__ void __launch_bounds__(256) k_gemm(const float* __restrict__ Wl, int resid) {
    __shared__ float sW[64 * 64];
    __shared__ float sS[64 * 68];
    int b = blockIdx.x;
    int j = 0;
    while (b >= c_GBLK[j + 1]) ++j;
    int rowBase = (b - c_GBLK[j]) * 64;
    int Nj = c_JN[j];
    int tid = threadIdx.x;
    int cq = tid & 15, rq = tid >> 4;
    int c0 = cq * 4, r0 = rq * 4;

    ull accA[4] = {0, 0, 0, 0};
    ull accB[4] = {0, 0, 0, 0};

    int np = c_NPJ[j];
    for (int p = 0; p < np; ++p) {
        int k = c_PAIRK[j][p];
        const float* W = Wl + (size_t)k * 4096;
        const float* S = g_S + (size_t)(c_SOFF[k] + rowBase) * C;
        for (int t = tid; t < 4096; t += 256) sW[t] = __ldg(W + t);
        for (int t = tid; t < 4096; t += 256) {
            int r = t >> 6, c = t & 63;
            sS[r * 68 + c] = (rowBase + r < Nj) ? S[(size_t)r * C + c] : 0.f;
        }
        __syncthreads();
        #pragma unroll 4
        for (int a0 = 0; a0 < 64; a0 += 4) {
            float4 s4[4];
            ulonglong2 w2[4];
            #pragma unroll
            for (int q = 0; q < 4; ++q)
                s4[q] = *(const float4*)(sS + (r0 + q) * 68 + a0);
            #pragma unroll
            for (int t = 0; t < 4; ++t)
                w2[t] = *(const ulonglong2*)(sW + (a0 + t) * 64 + c0);
            #pragma unroll
            for (int t = 0; t < 4; ++t) {
                #pragma unroll
                for (int q = 0; q < 4; ++q) {
                    float sv = ((const float*)&s4[q])[t];
                    ull sd = dup2(sv);
                    fma2(accA[q], sd, w2[t].x);
                    fma2(accB[q], sd, w2[t].y);
                }
            }
        }
        __syncthreads();
    }

    float* X = g_X + (size_t)c_JXO[j] * C;
    #pragma unroll
    for (int q = 0; q < 4; ++q) {
        int gr = rowBase + r0 + q;
        if (gr < Nj) {
            float2 lo = unpack2(accA[q]);
            float2 hi = unpack2(accB[q]);
            float4 o = make_float4(lo.x, lo.y, hi.x, hi.y);
            if (resid) {
                float4 x = *(const float4*)(X + (size_t)gr * C + c0);
                o.x += x.x; o.y += x.y; o.z += x.z; o.w += x.w;
            }
            o.x = fmaxf(o.x, 0.f); o.y = fmaxf(o.y, 0.f);
            o.z = fmaxf(o.z, 0.f); o.w = fmaxf(o.w, 0.f);
            *(float4*)(X + (size_t)gr * C + c0) = o;
        }
    }
}

// ---------------- pooling ----------------
__global__ void k_pool_init() {
    int t = threadIdx.x;
    if (t < 320) {
        g_sum[t] = 0.f; g_sq[t] = 0.f;
        g_mx[t] = 0x80000000; g_mn[t] = 0x7fffffff;
    }
}
__global__ void k_pool() {
    int rank = blockIdx.y;
    int c = threadIdx.x & 63;
    int rg = threadIdx.x >> 6;
    int Nr = c_N5[rank];
    const float* base = g_X + (size_t)c_JXO[rank] * C;
    float s = 0.f, sq = 0.f, mx = -3.402823466e38f, mn = 3.402823466e38f;
    for (int r = blockIdx.x * 4 + rg; r < Nr; r += gridDim.x * 4) {
        float v = base[(size_t)r * C + c];
        s += v; sq = fmaf(v, v, sq);
        mx = fmaxf(mx, v); mn = fminf(mn, v);
    }
    int o = rank * 64 + c;
    atomicAdd(&g_sum[o], s);
    atomicAdd(&g_sq[o], sq);
    atomicMax(&g_mx[o], fenc(mx));
    atomicMin(&g_mn[o], fenc(mn));
}
__global__ void k_pool_fin(const float* __restrict__ gf) {
    int idx = blockIdx.x * blockDim.x + threadIdx.x;
    if (idx >= 1284) return;
    if (idx >= 1280) { g_pooled[idx] = gf[idx - 1280]; return; }
    int rank = idx >> 8;
    int part = (idx >> 6) & 3;
    int c = idx & 63;
    int o = rank * 64 + c;
    float Nr = (float)c_N5[rank];
    float val;
    if (part == 0) val = g_sum[o] / Nr;
    else if (part == 1) {
        float m = g_sum[o] / Nr;
        float var = g_sq[o] / Nr - m * m;
        var = fmaxf(var, 0.f);
        if (var == 0.f) var = 1e-6f;
        val = sqrtf(var);
    } else if (part == 2) val = fdec(g_mx[o]);
    else val = fdec(g_mn[o]);
    g_pooled[idx] = val;
}

// ---------------- MLP head ----------------
__global__ void k_fc1(const float* __restrict__ w, const float* __restrict__ b) {
    __shared__ float p[1284];
    __shared__ float red[256];
    for (int i = threadIdx.x; i < 1284; i += 256) p[i] = g_pooled[i];
    __syncthreads();
    int lane = threadIdx.x & 31;
    int rp = threadIdx.x >> 5;
    int o = blockIdx.x * 32 + lane;
    float s = 0.f;
    for (int i = rp; i < 1284; i += 8) s = fmaf(p[i], w[(size_t)i * 512 + o], s);
    red[threadIdx.x] = s;
    __syncthreads();
    if (rp == 0) {
        float t = s;
        #pragma unroll
        for (int q = 1; q < 8; ++q) t += red[q * 32 + lane];
        t += b[o];
        g_h1[o] = fmaxf(t, 0.f);
    }
}
__global__ void k_tail(const float* __restrict__ w2, const float* __restrict__ b2,
                       const float* __restrict__ w3, const float* __restrict__ b3,
                       const float* __restrict__ w4, const float* __restrict__ b4,
                       float* __restrict__ out) {
    __shared__ float h2[128];
    __shared__ float h3[64];
    int tid = threadIdx.x;
    {
        float s = b2[tid];
        for (int i = 0; i < 512; ++i) s = fmaf(g_h1[i], w2[(size_t)i * 128 + tid], s);
        h2[tid] = fmaxf(s, 0.f);
    }
    __syncthreads();
    if (tid < 64) {
        float s = b3[tid];
        for (int i = 0; i < 128; ++i) s = fmaf(h2[i], w3[(size_t)i * 64 + tid], s);
        h3[tid] = fmaxf(s, 0.f);
    }
    __syncthreads();
    if (tid < 2) {
        float s = b4[tid];
        for (int i = 0; i < 64; ++i) s = fmaf(h3[i], w4[(size_t)i * 2 + tid], s);
        out[tid] = (tid == 0) ? s : s * s;
    }
}

// ---------------- host launcher ----------------
extern "C" void kernel_launch(void* const* d_in, const int* in_sizes, int n_in,
                              void* d_out, int out_size) {
    const float* xin[5] = {(const float*)d_in[0], (const float*)d_in[1],
                           (const float*)d_in[2], (const float*)d_in[3],
                           (const float*)d_in[4]};
    const int*   rows = (const int*)d_in[5];
    const int*   cols = (const int*)d_in[6];
    const float* vals = (const float*)d_in[7];
    const float* gf   = (const float*)d_in[8];
    const float* Whmc = (const float*)d_in[9];
    const float* fc1w = (const float*)d_in[10];
    const float* fc1b = (const float*)d_in[11];
    const float* fc2w = (const float*)d_in[12];
    const float* fc2b = (const float*)d_in[13];
    const float* fc3w = (const float*)d_in[14];
    const float* fc3b = (const float*)d_in[15];
    const float* fc4w = (const float*)d_in[16];
    const float* fc4b = (const float*)d_in[17];
    float* out = (float*)d_out;

    // resolve g_X device address for layer>0 agg sources
    static float* h_gX = nullptr;
    if (!h_gX) cudaGetSymbolAddress((void**)&h_gX, g_X);

    AggParams P0, P1;
    for (int k = 0; k < 15; ++k) {
        P0.src[k] = xin[H_PI[k]];
        P1.src[k] = h_gX + (size_t)H_XOFF[H_PI[k]] * C;
    }

    k_span_fill<<<792, 256>>>();
    k_span_mark<<<4096, 256>>>(rows);

    int* d_wspan; cudaGetSymbolAddress((void**)&d_wspan, g_wspan);

    for (int l = 0; l < 3; ++l) {
        k_agg<<<25313, 256>>>((l == 0) ? P0 : P1, rows, cols, vals, d_wspan);
        k_gemm<<<4846, 256>>>(Whmc + (size_t)l * 15 * 4096, (l == 2) ? 1 : 0);
    }

    k_pool_init<<<1, 320>>>();
    k_pool<<<dim3(32, 5), 256>>>();
    k_pool_fin<<<6, 256>>>(gf);
    k_fc1<<<16, 256>>>(fc1w, fc1b);
    k_tail<<<1, 128>>>(fc2w, fc2b, fc3w, fc3b, fc4w, fc4b, out);
}